// round 16
// baseline (speedup 1.0000x reference)
#include <cuda_runtime.h>
#include <math.h>

#define T_LEN   8192
#define F_DIM   8
#define B_SZ    128
#define NLAGS   24
#define THREADS 512                 // 256 loaders + 256 compute
#define LTHREADS 256
#define CTHREADS 256
#define NLW     8                   // loader warps
#define NCW     8                   // compute warps
#define HALF    4096
#define BND     NLAGS               // boundary lookahead loaded with phase 0
#define CHUNK   (HALF / CTHREADS)   // 16 elements per compute thread per phase
#define WIN     (CHUNK + NLAGS)     // 40-element register window

__device__ float g_partials[B_SZ];
__device__ int   g_count = 0;

// padded smem index: kills bank conflicts on stride-16 window loads
__device__ __forceinline__ int zi(int t) { return t + (t >> 5); }

__device__ __forceinline__ void bar_arrive(int id, int cnt) {
    asm volatile("bar.arrive %0, %1;" :: "r"(id), "r"(cnt) : "memory");
}
__device__ __forceinline__ void bar_wait(int id, int cnt) {
    asm volatile("bar.sync %0, %1;" :: "r"(id), "r"(cnt) : "memory");
}

__global__ __launch_bounds__(THREADS)
void autocorr_kernel(const float* __restrict__ input,
                     const float* __restrict__ lagw,
                     const float* __restrict__ seas,
                     float* __restrict__ out) {
    __shared__ float zs[T_LEN + (T_LEN >> 5)];
    __shared__ float red[2 * NLW];
    __shared__ float warp_sxy[NCW][NLAGS];

    const int b    = blockIdx.x;
    const int tid  = threadIdx.x;
    const int warp = tid >> 5;
    const int lane = tid & 31;
    const float* row = input + (size_t)b * T_LEN * F_DIM;

    if (tid < LTHREADS) {
        // ================= LOADER ROLE (warps 0-7) =================
        const int lt = tid;
        float lsum = 0.f, lsq = 0.f;

        // phase 0: [0, 4096) + boundary [4096, 4120)
        #pragma unroll
        for (int k = 0; k < CHUNK; k++) {
            int t = lt + k * LTHREADS;
            float v = __ldg(row + (size_t)t * F_DIM);
            zs[zi(t)] = v;
            lsum += v;
            lsq  += v * v;
        }
        if (lt < BND) {
            int t = HALF + lt;
            float v = __ldg(row + (size_t)t * F_DIM);
            zs[zi(t)] = v;
            lsum += v;          // counted once, here
            lsq  += v * v;
        }
        bar_arrive(1, THREADS);   // phase-0 data ready

        // phase 1: [4120, 8192)  (4072 elements, last iter predicated)
        #pragma unroll
        for (int k = 0; k < CHUNK; k++) {
            int t = HALF + BND + lt + k * LTHREADS;
            if (t < T_LEN) {
                float v = __ldg(row + (size_t)t * F_DIM);
                zs[zi(t)] = v;
                lsum += v;
                lsq  += v * v;
            }
        }
        bar_arrive(2, THREADS);   // phase-1 data ready

        // S/Q reduction (overlaps compute warps' phase-1 math)
        #pragma unroll
        for (int o = 16; o > 0; o >>= 1) {
            lsum += __shfl_xor_sync(0xffffffffu, lsum, o);
            lsq  += __shfl_xor_sync(0xffffffffu, lsq,  o);
        }
        if (lane == 0) { red[warp] = lsum; red[NLW + warp] = lsq; }
    } else {
        // ================= COMPUTE ROLE (warps 8-15) =================
        const int ct = tid - LTHREADS;
        const int cw = warp - NLW;
        float acc[NLAGS];
        #pragma unroll
        for (int l = 0; l < NLAGS; l++) acc[l] = 0.f;
        float w[WIN];

        // phase 0: windows starting in [0, 4096); needs up to 4119 (boundary)
        bar_wait(1, THREADS);
        {
            const int i0 = ct * CHUNK;
            #pragma unroll
            for (int j = 0; j < WIN; j++) w[j] = zs[zi(i0 + j)];   // max 4119 ✓
            #pragma unroll
            for (int j = 0; j < CHUNK; j++) {
                #pragma unroll
                for (int l = 0; l < NLAGS; l++)
                    acc[l] = fmaf(w[j], w[j + l + 1], acc[l]);
            }
        }

        // phase 1: windows starting in [4096, 8192); zero-pad past end
        bar_wait(2, THREADS);
        {
            const int i0 = HALF + ct * CHUNK;
            #pragma unroll
            for (int j = 0; j < WIN; j++) {
                int idx = i0 + j;
                w[j] = (idx < T_LEN) ? zs[zi(idx)] : 0.f;
            }
            #pragma unroll
            for (int j = 0; j < CHUNK; j++) {
                #pragma unroll
                for (int l = 0; l < NLAGS; l++)
                    acc[l] = fmaf(w[j], w[j + l + 1], acc[l]);
            }
        }

        // per-lag reduction: warp shuffle -> smem
        #pragma unroll
        for (int l = 0; l < NLAGS; l++) {
            float v = acc[l];
            #pragma unroll
            for (int o = 16; o > 0; o >>= 1)
                v += __shfl_xor_sync(0xffffffffu, v, o);
            if (lane == 0) warp_sxy[cw][l] = v;
        }
    }

    __syncthreads();   // red + warp_sxy + zs all visible

    // ---- epilogue: warp 0 finishes the whole row ----
    if (warp == 0) {
        float e = (lane < NLAGS) ? __expf(__ldg(lagw + lane)) : 0.f;
        float se = e;
        #pragma unroll
        for (int o = 16; o > 0; o >>= 1) se += __shfl_xor_sync(0xffffffffu, se, o);
        float coef = e / se;
        if (lane == 11) coef += __ldg(seas + 0);   // lag 12
        if (lane == 23) coef += __ldg(seas + 1);   // lag 24

        float val = 0.f;
        if (lane < NLAGS) {
            const int l   = lane;
            const int lag = l + 1;
            float sxy = 0.f;
            #pragma unroll
            for (int wi = 0; wi < NCW; wi++) sxy += warp_sxy[wi][l];

            float S = 0.f, Q = 0.f;
            #pragma unroll
            for (int i = 0; i < NLW; i++) { S += red[i]; Q += red[NLW + i]; }

            float hs = 0.f, hq = 0.f, ts = 0.f, tq = 0.f;
            for (int t = 0; t < lag; t++)            { float v = zs[zi(t)]; hs += v; hq += v * v; }
            for (int t = T_LEN - lag; t < T_LEN; t++){ float v = zs[zi(t)]; ts += v; tq += v * v; }

            const float Sx  = S - ts,  Sy  = S - hs;
            const float Sxx = Q - tq,  Syy = Q - hq;
            const float n   = (float)(T_LEN - lag);

            float num = sxy - Sx * Sy / n;
            float vx  = Sxx - Sx * Sx / n;
            float vy  = Syy - Sy * Sy / n;
            float r   = num / (sqrtf(fmaxf(vx, 0.f)) * sqrtf(fmaxf(vy, 0.f)));
            r = fminf(1.f, fmaxf(-1.f, r));
            val = r * coef;
        }
        #pragma unroll
        for (int o = 16; o > 0; o >>= 1) val += __shfl_xor_sync(0xffffffffu, val, o);

        int ticket = 0;
        if (lane == 0) {
            g_partials[b] = val;
            __threadfence();
            ticket = atomicAdd(&g_count, 1);
        }
        ticket = __shfl_sync(0xffffffffu, ticket, 0);

        if (ticket == B_SZ - 1) {   // last block folds the 128 row partials
            __threadfence();
            float s = g_partials[lane] + g_partials[lane + 32]
                    + g_partials[lane + 64] + g_partials[lane + 96];
            #pragma unroll
            for (int o = 16; o > 0; o >>= 1) s += __shfl_xor_sync(0xffffffffu, s, o);
            if (lane == 0) {
                out[0] = s * (1.f / (float)B_SZ);
                g_count = 0;   // reset for next graph replay
            }
        }
    }
}

extern "C" void kernel_launch(void* const* d_in, const int* in_sizes, int n_in,
                              void* d_out, int out_size) {
    const float* input = (const float*)d_in[0];   // input_sequence (128,8192,8)
    // d_in[1] = hidden_states — never referenced by the math; intentionally unused
    const float* lagw  = (const float*)d_in[2];   // lag_weights (24,)
    const float* seas  = (const float*)d_in[3];   // seasonal_importance (2,)
    float* out = (float*)d_out;

    autocorr_kernel<<<B_SZ, THREADS>>>(input, lagw, seas, out);
}